// round 3
// baseline (speedup 1.0000x reference)
#include <cuda_runtime.h>
#include <cuda_bf16.h>

#define CCH 256        // channels
#define LV 2           // levels
#define NP 4           // points
#define NOFF 16        // offset outputs (LV*NP*2)
#define NAW 8          // attn outputs (LV*NP)
#define NOUT 24        // total projection outputs
#define WPB 8          // warps per block (sampling kernel)
#define K1_BLOCK 64    // threads per block (projection kernel)

// Scratch: per-query projection results {16 raw offsets, 8 normalized attn w}.
__device__ float g_P[1 << 21];   // 8.4 MB, supports Q up to ~87k

// ---------------------------------------------------------------------------
// Kernel 1: projection + softmax.  thread = query.
// Weight reads are warp-uniform LDS.128 broadcasts (1 wavefront / 32 queries).
// Packed f32x2 FMA halves the FMA instruction count.
// ---------------------------------------------------------------------------
__global__ __launch_bounds__(K1_BLOCK)
void proj_kernel(const float* __restrict__ query,
                 const float* __restrict__ W_off,  const float* __restrict__ b_off,
                 const float* __restrict__ W_attn, const float* __restrict__ b_attn,
                 int Q)
{
    __shared__ float wsh[CCH * NOUT];   // layout [c][24], rows 96B (16B aligned)

    for (int i = threadIdx.x; i < CCH * NOFF; i += K1_BLOCK) {
        int c = i >> 4, j = i & 15;                 // W_off row-major [C,16]
        wsh[c * NOUT + j] = W_off[i];
    }
    for (int i = threadIdx.x; i < CCH * NAW; i += K1_BLOCK) {
        int c = i >> 3, j = i & 7;                  // W_attn row-major [C,8]
        wsh[c * NOUT + NOFF + j] = W_attn[i];
    }
    __syncthreads();

    const int q = blockIdx.x * K1_BLOCK + threadIdx.x;
    if (q >= Q) return;

    unsigned long long acc[12];
#pragma unroll
    for (int i = 0; i < 12; i++) acc[i] = 0ull;

    unsigned wa = (unsigned)__cvta_generic_to_shared(wsh);
    const float4* q4 = (const float4*)(query + (size_t)q * CCH);

#define PROJ_STEP(QC)                                                          \
    do {                                                                       \
        unsigned long long qc2;                                                \
        asm("mov.b64 %0, {%1, %1};" : "=l"(qc2) : "f"(QC));                    \
        unsigned long long w0,w1,w2,w3,w4,w5,w6,w7,w8,w9,wA,wB;                \
        asm volatile("ld.shared.v2.u64 {%0,%1}, [%2];"    : "=l"(w0),"=l"(w1) : "r"(wa)); \
        asm volatile("ld.shared.v2.u64 {%0,%1}, [%2+16];" : "=l"(w2),"=l"(w3) : "r"(wa)); \
        asm volatile("ld.shared.v2.u64 {%0,%1}, [%2+32];" : "=l"(w4),"=l"(w5) : "r"(wa)); \
        asm volatile("ld.shared.v2.u64 {%0,%1}, [%2+48];" : "=l"(w6),"=l"(w7) : "r"(wa)); \
        asm volatile("ld.shared.v2.u64 {%0,%1}, [%2+64];" : "=l"(w8),"=l"(w9) : "r"(wa)); \
        asm volatile("ld.shared.v2.u64 {%0,%1}, [%2+80];" : "=l"(wA),"=l"(wB) : "r"(wa)); \
        asm("fma.rn.f32x2 %0, %1, %2, %0;" : "+l"(acc[0])  : "l"(w0), "l"(qc2)); \
        asm("fma.rn.f32x2 %0, %1, %2, %0;" : "+l"(acc[1])  : "l"(w1), "l"(qc2)); \
        asm("fma.rn.f32x2 %0, %1, %2, %0;" : "+l"(acc[2])  : "l"(w2), "l"(qc2)); \
        asm("fma.rn.f32x2 %0, %1, %2, %0;" : "+l"(acc[3])  : "l"(w3), "l"(qc2)); \
        asm("fma.rn.f32x2 %0, %1, %2, %0;" : "+l"(acc[4])  : "l"(w4), "l"(qc2)); \
        asm("fma.rn.f32x2 %0, %1, %2, %0;" : "+l"(acc[5])  : "l"(w5), "l"(qc2)); \
        asm("fma.rn.f32x2 %0, %1, %2, %0;" : "+l"(acc[6])  : "l"(w6), "l"(qc2)); \
        asm("fma.rn.f32x2 %0, %1, %2, %0;" : "+l"(acc[7])  : "l"(w7), "l"(qc2)); \
        asm("fma.rn.f32x2 %0, %1, %2, %0;" : "+l"(acc[8])  : "l"(w8), "l"(qc2)); \
        asm("fma.rn.f32x2 %0, %1, %2, %0;" : "+l"(acc[9])  : "l"(w9), "l"(qc2)); \
        asm("fma.rn.f32x2 %0, %1, %2, %0;" : "+l"(acc[10]) : "l"(wA), "l"(qc2)); \
        asm("fma.rn.f32x2 %0, %1, %2, %0;" : "+l"(acc[11]) : "l"(wB), "l"(qc2)); \
        wa += NOUT * 4;                                                        \
    } while (0)

#pragma unroll 2
    for (int k4 = 0; k4 < CCH / 4; k4++) {
        const float4 qv = __ldg(q4 + k4);
        PROJ_STEP(qv.x);
        PROJ_STEP(qv.y);
        PROJ_STEP(qv.z);
        PROJ_STEP(qv.w);
    }
#undef PROJ_STEP

    float p[NOUT];
#pragma unroll
    for (int i = 0; i < 12; i++) {
        float lo, hi;
        asm("mov.b64 {%0, %1}, %2;" : "=f"(lo), "=f"(hi) : "l"(acc[i]));
        p[2 * i] = lo; p[2 * i + 1] = hi;
    }
#pragma unroll
    for (int j = 0; j < NOFF; j++) p[j] += __ldg(b_off + j);
#pragma unroll
    for (int j = 0; j < NAW; j++)  p[NOFF + j] += __ldg(b_attn + j);

    // softmax over the 8 attn logits (store normalized)
    float m = p[NOFF];
#pragma unroll
    for (int j = 1; j < NAW; j++) m = fmaxf(m, p[NOFF + j]);
    float s = 0.f;
#pragma unroll
    for (int j = 0; j < NAW; j++) {
        const float e = __expf(p[NOFF + j] - m);
        p[NOFF + j] = e;
        s += e;
    }
    const float inv = 1.f / s;
#pragma unroll
    for (int j = 0; j < NAW; j++) p[NOFF + j] *= inv;

    float4* o4 = (float4*)(g_P + (size_t)q * NOUT);
#pragma unroll
    for (int i = 0; i < 6; i++)
        o4[i] = make_float4(p[4 * i], p[4 * i + 1], p[4 * i + 2], p[4 * i + 3]);
}

// ---------------------------------------------------------------------------
// Kernel 2: bilinear sampling + weighted accumulation.  warp = query.
// ---------------------------------------------------------------------------
__global__ __launch_bounds__(WPB * 32, 5)
void sample_kernel(const float* __restrict__ value,
                   const float* __restrict__ refpts,
                   const int*   __restrict__ shapes_raw,
                   float* __restrict__ out, int Q)
{
    const int tid  = threadIdx.x;
    const int lane = tid & 31;
    const int q = blockIdx.x * WPB + (tid >> 5);
    if (q >= Q) return;

    // decode spatial shapes (int64 little-endian -> odd int32 slots are 0)
    int HH[LV], WW[LV];
    {
        const int st = (__ldg(shapes_raw + 1) == 0) ? 2 : 1;
#pragma unroll
        for (int l = 0; l < LV; l++) {
            HH[l] = __ldg(shapes_raw + (2 * l) * st);
            WW[l] = __ldg(shapes_raw + (2 * l + 1) * st);
        }
    }

    const float4* pf  = (const float4*)(g_P + (size_t)q * NOUT);
    const float*  ref = refpts + (size_t)q * (LV * 2);

    float4 acc0 = make_float4(0.f, 0.f, 0.f, 0.f);
    float4 acc1 = make_float4(0.f, 0.f, 0.f, 0.f);
    size_t loff = 0;

#pragma unroll
    for (int l = 0; l < LV; l++) {
        const int Hs = HH[l], Ws = WW[l];
        const float fW = (float)Ws, fH = (float)Hs;
        // ix = (rx + ox/W)*W - 0.5 == rx*W + ox - 0.5  (fp reassoc, ok at 1e-3)
        const float bx = __ldg(ref + 2 * l)     * fW - 0.5f;
        const float by = __ldg(ref + 2 * l + 1) * fH - 0.5f;

        const float4 o0 = __ldg(pf + 2 * l);       // offsets pts 0,1 (x,y,x,y)
        const float4 o1 = __ldg(pf + 2 * l + 1);   // offsets pts 2,3
        const float4 wv = __ldg(pf + 4 + l);       // 4 normalized attn weights
        const float* vb = value + loff;

        const float oxs[NP] = {o0.x, o0.z, o1.x, o1.z};
        const float oys[NP] = {o0.y, o0.w, o1.y, o1.w};
        const float aws[NP] = {wv.x, wv.y, wv.z, wv.w};

#pragma unroll
        for (int pt = 0; pt < NP; pt++) {
            const float ix = bx + oxs[pt];
            const float iy = by + oys[pt];
            const float x0f = floorf(ix);
            const float y0f = floorf(iy);
            const int x0 = (int)x0f;
            const int y0 = (int)y0f;
            const float fx = ix - x0f;
            const float fy = iy - y0f;
            const float a = aws[pt];

            const float w00 = (1.f - fx) * (1.f - fy) * a;
            const float w01 = fx * (1.f - fy) * a;
            const float w10 = (1.f - fx) * fy * a;
            const float w11 = fx * fy * a;

#define CORNER(XX, YY, W)                                                      \
            if ((unsigned)(XX) < (unsigned)Ws && (unsigned)(YY) < (unsigned)Hs) { \
                const float4* vp = (const float4*)(vb + ((size_t)(YY) * Ws + (XX)) * CCH); \
                const float4 v0 = __ldg(vp + lane * 2 + 0);                    \
                const float4 v1 = __ldg(vp + lane * 2 + 1);                    \
                acc0.x = fmaf((W), v0.x, acc0.x);                              \
                acc0.y = fmaf((W), v0.y, acc0.y);                              \
                acc0.z = fmaf((W), v0.z, acc0.z);                              \
                acc0.w = fmaf((W), v0.w, acc0.w);                              \
                acc1.x = fmaf((W), v1.x, acc1.x);                              \
                acc1.y = fmaf((W), v1.y, acc1.y);                              \
                acc1.z = fmaf((W), v1.z, acc1.z);                              \
                acc1.w = fmaf((W), v1.w, acc1.w);                              \
            }

            CORNER(x0,     y0,     w00);
            CORNER(x0 + 1, y0,     w01);
            CORNER(x0,     y0 + 1, w10);
            CORNER(x0 + 1, y0 + 1, w11);
#undef CORNER
        }
        loff += (size_t)Hs * (size_t)Ws * CCH;
    }

    float4* op = (float4*)(out + (size_t)q * CCH);
    op[lane * 2 + 0] = acc0;
    op[lane * 2 + 1] = acc1;
}

extern "C" void kernel_launch(void* const* d_in, const int* in_sizes, int n_in,
                              void* d_out, int out_size)
{
    const float* query   = (const float*)d_in[0];
    // d_in[1] = key (unused)
    const float* value   = (const float*)d_in[2];
    const float* refpts  = (const float*)d_in[3];
    const int*   shapes  = (const int*)d_in[4];
    const float* W_off   = (const float*)d_in[5];
    const float* b_off   = (const float*)d_in[6];
    const float* W_attn  = (const float*)d_in[7];
    const float* b_attn  = (const float*)d_in[8];
    float*       out     = (float*)d_out;

    const int Q = in_sizes[0] / CCH;

    proj_kernel<<<(Q + K1_BLOCK - 1) / K1_BLOCK, K1_BLOCK>>>(
        query, W_off, b_off, W_attn, b_attn, Q);
    sample_kernel<<<(Q + WPB - 1) / WPB, WPB * 32>>>(
        value, refpts, shapes, out, Q);
}

// round 4
// speedup vs baseline: 1.6857x; 1.6857x over previous
#include <cuda_runtime.h>
#include <cuda_bf16.h>

#define CCH 256        // channels
#define LV 2           // levels
#define NP 4           // points
#define NOFF 16        // offset outputs (LV*NP*2)
#define NAW 8          // attn outputs (LV*NP)
#define NOUT 24        // total projection outputs
#define WPB 8          // warps per block (sampling kernel)

// Scratch: per-query projection results {16 raw offsets, 8 normalized attn w}.
__device__ float g_P[1 << 21];   // 8.4 MB, supports Q up to ~87k

// ---------------------------------------------------------------------------
// Kernel 1: projection + softmax.  thread = query. Plain C++ — weight reads
// are warp-uniform LDS broadcasts; ptxas pipelines the loop.
// ---------------------------------------------------------------------------
__global__ __launch_bounds__(256)
void proj_kernel(const float* __restrict__ query,
                 const float* __restrict__ W_off,  const float* __restrict__ b_off,
                 const float* __restrict__ W_attn, const float* __restrict__ b_attn,
                 int Q)
{
    __shared__ float wsh[CCH * NOUT];   // [c][24]

    for (int i = threadIdx.x; i < CCH * NOFF; i += 256) {
        int c = i >> 4, j = i & 15;                 // W_off row-major [C,16]
        wsh[c * NOUT + j] = W_off[i];
    }
    for (int i = threadIdx.x; i < CCH * NAW; i += 256) {
        int c = i >> 3, j = i & 7;                  // W_attn row-major [C,8]
        wsh[c * NOUT + NOFF + j] = W_attn[i];
    }
    __syncthreads();

    const int q = blockIdx.x * 256 + threadIdx.x;
    if (q >= Q) return;

    float p[NOUT];
#pragma unroll
    for (int j = 0; j < NOFF; j++) p[j] = __ldg(b_off + j);
#pragma unroll
    for (int j = 0; j < NAW; j++)  p[NOFF + j] = __ldg(b_attn + j);

    const float4* q4 = (const float4*)(query + (size_t)q * CCH);
#pragma unroll 2
    for (int k = 0; k < CCH / 4; k++) {
        const float4 qv = __ldg(q4 + k);
        const float* w0 = &wsh[(4 * k) * NOUT];
#pragma unroll
        for (int j = 0; j < NOUT; j++) p[j] = fmaf(qv.x, w0[j],            p[j]);
#pragma unroll
        for (int j = 0; j < NOUT; j++) p[j] = fmaf(qv.y, w0[NOUT + j],     p[j]);
#pragma unroll
        for (int j = 0; j < NOUT; j++) p[j] = fmaf(qv.z, w0[2 * NOUT + j], p[j]);
#pragma unroll
        for (int j = 0; j < NOUT; j++) p[j] = fmaf(qv.w, w0[3 * NOUT + j], p[j]);
    }

    // softmax over the 8 attn logits (store normalized)
    float m = p[NOFF];
#pragma unroll
    for (int j = 1; j < NAW; j++) m = fmaxf(m, p[NOFF + j]);
    float s = 0.f;
#pragma unroll
    for (int j = 0; j < NAW; j++) {
        const float e = __expf(p[NOFF + j] - m);
        p[NOFF + j] = e;
        s += e;
    }
    const float inv = 1.f / s;
#pragma unroll
    for (int j = 0; j < NAW; j++) p[NOFF + j] *= inv;

    float4* o4 = (float4*)(g_P + (size_t)q * NOUT);
#pragma unroll
    for (int i = 0; i < 6; i++)
        o4[i] = make_float4(p[4 * i], p[4 * i + 1], p[4 * i + 2], p[4 * i + 3]);
}

// ---------------------------------------------------------------------------
// Kernel 2: bilinear sampling with corner deduplication.  warp = query.
// The 16 corners (4 pts x 4 corners) of a level nearly always fit a 4x4
// pixel window; accumulate cell weights in registers (lane i owns cell i),
// then gather only cells with nonzero weight.
// ---------------------------------------------------------------------------
__global__ __launch_bounds__(WPB * 32, 5)
void sample_kernel(const float* __restrict__ value,
                   const float* __restrict__ refpts,
                   const int*   __restrict__ shapes_raw,
                   float* __restrict__ out, int Q)
{
    const int tid  = threadIdx.x;
    const int lane = tid & 31;
    const int q = blockIdx.x * WPB + (tid >> 5);
    if (q >= Q) return;

    // decode spatial shapes (int64 little-endian -> odd int32 slots are 0)
    int HH[LV], WW[LV];
    {
        const int st = (__ldg(shapes_raw + 1) == 0) ? 2 : 1;
#pragma unroll
        for (int l = 0; l < LV; l++) {
            HH[l] = __ldg(shapes_raw + (2 * l) * st);
            WW[l] = __ldg(shapes_raw + (2 * l + 1) * st);
        }
    }

    const float4* pf  = (const float4*)(g_P + (size_t)q * NOUT);
    const float*  ref = refpts + (size_t)q * (LV * 2);

    float4 acc0 = make_float4(0.f, 0.f, 0.f, 0.f);
    float4 acc1 = make_float4(0.f, 0.f, 0.f, 0.f);
    size_t loff = 0;

#define GATHER(XX, YY, W)                                                      \
    do {                                                                       \
        const float4* vp = (const float4*)(vb + ((size_t)(YY) * Ws + (XX)) * CCH); \
        const float4 v0 = __ldg(vp + lane * 2 + 0);                            \
        const float4 v1 = __ldg(vp + lane * 2 + 1);                            \
        acc0.x = fmaf((W), v0.x, acc0.x);                                      \
        acc0.y = fmaf((W), v0.y, acc0.y);                                      \
        acc0.z = fmaf((W), v0.z, acc0.z);                                      \
        acc0.w = fmaf((W), v0.w, acc0.w);                                      \
        acc1.x = fmaf((W), v1.x, acc1.x);                                      \
        acc1.y = fmaf((W), v1.y, acc1.y);                                      \
        acc1.z = fmaf((W), v1.z, acc1.z);                                      \
        acc1.w = fmaf((W), v1.w, acc1.w);                                      \
    } while (0)

#pragma unroll
    for (int l = 0; l < LV; l++) {
        const int Hs = HH[l], Ws = WW[l];
        // ix = (rx + ox/W)*W - 0.5 == rx*W + ox - 0.5
        const float bx = __ldg(ref + 2 * l)     * (float)Ws - 0.5f;
        const float by = __ldg(ref + 2 * l + 1) * (float)Hs - 0.5f;

        const float4 o0 = __ldg(pf + 2 * l);       // offsets pts 0,1 (x,y,x,y)
        const float4 o1 = __ldg(pf + 2 * l + 1);   // offsets pts 2,3
        const float4 wv = __ldg(pf + 4 + l);       // 4 normalized attn weights
        const float* vb = value + loff;

        const float oxs[NP] = {o0.x, o0.z, o1.x, o1.z};
        const float oys[NP] = {o0.y, o0.w, o1.y, o1.w};
        const float aws[NP] = {wv.x, wv.y, wv.z, wv.w};

        int   x0[NP], y0[NP];
        float cw[NP][4];   // w00, w01, w10, w11 per point
#pragma unroll
        for (int pt = 0; pt < NP; pt++) {
            const float ix = bx + oxs[pt];
            const float iy = by + oys[pt];
            const float x0f = floorf(ix);
            const float y0f = floorf(iy);
            x0[pt] = (int)x0f;
            y0[pt] = (int)y0f;
            const float fx = ix - x0f;
            const float fy = iy - y0f;
            const float a  = aws[pt];
            cw[pt][0] = (1.f - fx) * (1.f - fy) * a;
            cw[pt][1] = fx * (1.f - fy) * a;
            cw[pt][2] = (1.f - fx) * fy * a;
            cw[pt][3] = fx * fy * a;
        }

        const int xmin = min(min(x0[0], x0[1]), min(x0[2], x0[3]));
        const int ymin = min(min(y0[0], y0[1]), min(y0[2], y0[3]));
        const int xmax = max(max(x0[0], x0[1]), max(x0[2], x0[3]));
        const int ymax = max(max(y0[0], y0[1]), max(y0[2], y0[3]));

        if (xmax - xmin <= 2 && ymax - ymin <= 2) {
            // Fast path: all 16 corners live in a 4x4 window. Lane i holds the
            // accumulated weight of cell i (cell = dy*4 + dx).
            float myw = 0.f;
#pragma unroll
            for (int pt = 0; pt < NP; pt++) {
                const int b = (y0[pt] - ymin) * 4 + (x0[pt] - xmin);
                myw += (lane == b)     ? cw[pt][0] : 0.f;
                myw += (lane == b + 1) ? cw[pt][1] : 0.f;
                myw += (lane == b + 4) ? cw[pt][2] : 0.f;
                myw += (lane == b + 5) ? cw[pt][3] : 0.f;
            }
            unsigned nz = __ballot_sync(0xffffffffu, (lane < 16) && (myw != 0.f));
            while (nz) {
                const int cell = __ffs(nz) - 1;
                nz &= nz - 1;
                const float w = __shfl_sync(0xffffffffu, myw, cell);
                const int xx = xmin + (cell & 3);
                const int yy = ymin + (cell >> 2);
                if ((unsigned)xx < (unsigned)Ws && (unsigned)yy < (unsigned)Hs)
                    GATHER(xx, yy, w);
            }
        } else {
            // Rare fallback: per-point corner loads.
#pragma unroll
            for (int pt = 0; pt < NP; pt++) {
                const int xs[2] = {x0[pt], x0[pt] + 1};
                const int ys[2] = {y0[pt], y0[pt] + 1};
#pragma unroll
                for (int cy = 0; cy < 2; cy++) {
#pragma unroll
                    for (int cx = 0; cx < 2; cx++) {
                        const int xx = xs[cx];
                        const int yy = ys[cy];
                        const float w = cw[pt][cy * 2 + cx];
                        if ((unsigned)xx < (unsigned)Ws && (unsigned)yy < (unsigned)Hs)
                            GATHER(xx, yy, w);
                    }
                }
            }
        }
        loff += (size_t)Hs * (size_t)Ws * CCH;
    }
#undef GATHER

    float4* op = (float4*)(out + (size_t)q * CCH);
    op[lane * 2 + 0] = acc0;
    op[lane * 2 + 1] = acc1;
}

extern "C" void kernel_launch(void* const* d_in, const int* in_sizes, int n_in,
                              void* d_out, int out_size)
{
    const float* query   = (const float*)d_in[0];
    // d_in[1] = key (unused)
    const float* value   = (const float*)d_in[2];
    const float* refpts  = (const float*)d_in[3];
    const int*   shapes  = (const int*)d_in[4];
    const float* W_off   = (const float*)d_in[5];
    const float* b_off   = (const float*)d_in[6];
    const float* W_attn  = (const float*)d_in[7];
    const float* b_attn  = (const float*)d_in[8];
    float*       out     = (float*)d_out;

    const int Q = in_sizes[0] / CCH;

    proj_kernel<<<(Q + 255) / 256, 256>>>(query, W_off, b_off, W_attn, b_attn, Q);
    sample_kernel<<<(Q + WPB - 1) / WPB, WPB * 32>>>(value, refpts, shapes, out, Q);
}

// round 5
// speedup vs baseline: 1.8480x; 1.0963x over previous
#include <cuda_runtime.h>
#include <cuda_bf16.h>

#define CCH 256        // channels
#define LV 2           // levels
#define NP 4           // points
#define NOFF 16        // offset outputs (LV*NP*2)
#define NAW 8          // attn outputs (LV*NP)
#define NOUT 24        // total projection outputs
#define WPB 8          // warps per block (sampling kernel)
#define K1_BLOCK 128   // threads per block (projection kernel)

// Scratch: per-query projection results {16 raw offsets, 8 normalized attn w}.
__device__ float g_P[1 << 21];   // 8.4 MB, supports Q up to ~87k

// ---------------------------------------------------------------------------
// Kernel 1: projection + softmax.  thread = query.
// Weights staged [c][24] in smem; read as warp-uniform LDS.128 (ulonglong2),
// accumulated with packed fma.rn.f32x2 (12 FFMA2 per channel instead of 24
// FFMA). Asm is non-volatile / clobber-free so ptxas can pipeline freely.
// ---------------------------------------------------------------------------
__global__ __launch_bounds__(K1_BLOCK)
void proj_kernel(const float* __restrict__ query,
                 const float* __restrict__ W_off,  const float* __restrict__ b_off,
                 const float* __restrict__ W_attn, const float* __restrict__ b_attn,
                 int Q)
{
    __shared__ __align__(16) float wsh[CCH * NOUT];   // [c][24], rows 96B

    for (int i = threadIdx.x; i < CCH * NOFF; i += K1_BLOCK) {
        int c = i >> 4, j = i & 15;                 // W_off row-major [C,16]
        wsh[c * NOUT + j] = W_off[i];
    }
    for (int i = threadIdx.x; i < CCH * NAW; i += K1_BLOCK) {
        int c = i >> 3, j = i & 7;                  // W_attn row-major [C,8]
        wsh[c * NOUT + NOFF + j] = W_attn[i];
    }
    __syncthreads();

    const int q = blockIdx.x * K1_BLOCK + threadIdx.x;
    if (q >= Q) return;

    // Pack bias into 12 f32x2 accumulators.
    unsigned long long acc[12];
    {
        float pb[NOUT];
#pragma unroll
        for (int j = 0; j < NOFF; j++) pb[j] = __ldg(b_off + j);
#pragma unroll
        for (int j = 0; j < NAW; j++)  pb[NOFF + j] = __ldg(b_attn + j);
#pragma unroll
        for (int i = 0; i < 12; i++)
            asm("mov.b64 %0, {%1, %2};" : "=l"(acc[i]) : "f"(pb[2 * i]), "f"(pb[2 * i + 1]));
    }

    const float4* q4 = (const float4*)(query + (size_t)q * CCH);
    const char* wrow = (const char*)wsh;

#define PSTEP(QC)                                                              \
    do {                                                                       \
        unsigned long long q2;                                                 \
        asm("mov.b64 %0, {%1, %1};" : "=l"(q2) : "f"(QC));                     \
        const ulonglong2* w2 = (const ulonglong2*)wrow;                        \
        const ulonglong2 a0 = w2[0], a1 = w2[1], a2 = w2[2];                   \
        const ulonglong2 a3 = w2[3], a4 = w2[4], a5 = w2[5];                   \
        asm("fma.rn.f32x2 %0, %1, %2, %0;" : "+l"(acc[0])  : "l"(a0.x), "l"(q2)); \
        asm("fma.rn.f32x2 %0, %1, %2, %0;" : "+l"(acc[1])  : "l"(a0.y), "l"(q2)); \
        asm("fma.rn.f32x2 %0, %1, %2, %0;" : "+l"(acc[2])  : "l"(a1.x), "l"(q2)); \
        asm("fma.rn.f32x2 %0, %1, %2, %0;" : "+l"(acc[3])  : "l"(a1.y), "l"(q2)); \
        asm("fma.rn.f32x2 %0, %1, %2, %0;" : "+l"(acc[4])  : "l"(a2.x), "l"(q2)); \
        asm("fma.rn.f32x2 %0, %1, %2, %0;" : "+l"(acc[5])  : "l"(a2.y), "l"(q2)); \
        asm("fma.rn.f32x2 %0, %1, %2, %0;" : "+l"(acc[6])  : "l"(a3.x), "l"(q2)); \
        asm("fma.rn.f32x2 %0, %1, %2, %0;" : "+l"(acc[7])  : "l"(a3.y), "l"(q2)); \
        asm("fma.rn.f32x2 %0, %1, %2, %0;" : "+l"(acc[8])  : "l"(a4.x), "l"(q2)); \
        asm("fma.rn.f32x2 %0, %1, %2, %0;" : "+l"(acc[9])  : "l"(a4.y), "l"(q2)); \
        asm("fma.rn.f32x2 %0, %1, %2, %0;" : "+l"(acc[10]) : "l"(a5.x), "l"(q2)); \
        asm("fma.rn.f32x2 %0, %1, %2, %0;" : "+l"(acc[11]) : "l"(a5.y), "l"(q2)); \
        wrow += NOUT * 4;                                                      \
    } while (0)

#pragma unroll 2
    for (int k4 = 0; k4 < CCH / 4; k4++) {
        const float4 qv = __ldg(q4 + k4);
        PSTEP(qv.x);
        PSTEP(qv.y);
        PSTEP(qv.z);
        PSTEP(qv.w);
    }
#undef PSTEP

    float p[NOUT];
#pragma unroll
    for (int i = 0; i < 12; i++) {
        float lo, hi;
        asm("mov.b64 {%0, %1}, %2;" : "=f"(lo), "=f"(hi) : "l"(acc[i]));
        p[2 * i] = lo; p[2 * i + 1] = hi;
    }

    // softmax over the 8 attn logits (store normalized)
    float m = p[NOFF];
#pragma unroll
    for (int j = 1; j < NAW; j++) m = fmaxf(m, p[NOFF + j]);
    float s = 0.f;
#pragma unroll
    for (int j = 0; j < NAW; j++) {
        const float e = __expf(p[NOFF + j] - m);
        p[NOFF + j] = e;
        s += e;
    }
    const float inv = 1.f / s;
#pragma unroll
    for (int j = 0; j < NAW; j++) p[NOFF + j] *= inv;

    float4* o4 = (float4*)(g_P + (size_t)q * NOUT);
#pragma unroll
    for (int i = 0; i < 6; i++)
        o4[i] = make_float4(p[4 * i], p[4 * i + 1], p[4 * i + 2], p[4 * i + 3]);
}

// ---------------------------------------------------------------------------
// Kernel 2: bilinear sampling with corner deduplication.  warp = query.
// ---------------------------------------------------------------------------
__global__ __launch_bounds__(WPB * 32, 6)
void sample_kernel(const float* __restrict__ value,
                   const float* __restrict__ refpts,
                   const int*   __restrict__ shapes_raw,
                   float* __restrict__ out, int Q)
{
    const int tid  = threadIdx.x;
    const int lane = tid & 31;
    const int q = blockIdx.x * WPB + (tid >> 5);
    if (q >= Q) return;

    // decode spatial shapes (int64 little-endian -> odd int32 slots are 0)
    int HH[LV], WW[LV];
    {
        const int st = (__ldg(shapes_raw + 1) == 0) ? 2 : 1;
#pragma unroll
        for (int l = 0; l < LV; l++) {
            HH[l] = __ldg(shapes_raw + (2 * l) * st);
            WW[l] = __ldg(shapes_raw + (2 * l + 1) * st);
        }
    }

    const float4* pf  = (const float4*)(g_P + (size_t)q * NOUT);
    const float*  ref = refpts + (size_t)q * (LV * 2);

    float4 acc0 = make_float4(0.f, 0.f, 0.f, 0.f);
    float4 acc1 = make_float4(0.f, 0.f, 0.f, 0.f);
    size_t loff = 0;

#define GATHER(XX, YY, W)                                                      \
    do {                                                                       \
        const float4* vp = (const float4*)(vb + ((size_t)(YY) * Ws + (XX)) * CCH); \
        const float4 v0 = __ldg(vp + lane * 2 + 0);                            \
        const float4 v1 = __ldg(vp + lane * 2 + 1);                            \
        acc0.x = fmaf((W), v0.x, acc0.x);                                      \
        acc0.y = fmaf((W), v0.y, acc0.y);                                      \
        acc0.z = fmaf((W), v0.z, acc0.z);                                      \
        acc0.w = fmaf((W), v0.w, acc0.w);                                      \
        acc1.x = fmaf((W), v1.x, acc1.x);                                      \
        acc1.y = fmaf((W), v1.y, acc1.y);                                      \
        acc1.z = fmaf((W), v1.z, acc1.z);                                      \
        acc1.w = fmaf((W), v1.w, acc1.w);                                      \
    } while (0)

#pragma unroll
    for (int l = 0; l < LV; l++) {
        const int Hs = HH[l], Ws = WW[l];
        // ix = (rx + ox/W)*W - 0.5 == rx*W + ox - 0.5
        const float bx = __ldg(ref + 2 * l)     * (float)Ws - 0.5f;
        const float by = __ldg(ref + 2 * l + 1) * (float)Hs - 0.5f;

        const float4 o0 = __ldg(pf + 2 * l);       // offsets pts 0,1 (x,y,x,y)
        const float4 o1 = __ldg(pf + 2 * l + 1);   // offsets pts 2,3
        const float4 wv = __ldg(pf + 4 + l);       // 4 normalized attn weights
        const float* vb = value + loff;

        const float oxs[NP] = {o0.x, o0.z, o1.x, o1.z};
        const float oys[NP] = {o0.y, o0.w, o1.y, o1.w};
        const float aws[NP] = {wv.x, wv.y, wv.z, wv.w};

        int   x0[NP], y0[NP];
        float cw[NP][4];   // w00, w01, w10, w11 per point
#pragma unroll
        for (int pt = 0; pt < NP; pt++) {
            const float ix = bx + oxs[pt];
            const float iy = by + oys[pt];
            const float x0f = floorf(ix);
            const float y0f = floorf(iy);
            x0[pt] = (int)x0f;
            y0[pt] = (int)y0f;
            const float fx = ix - x0f;
            const float fy = iy - y0f;
            const float a  = aws[pt];
            cw[pt][0] = (1.f - fx) * (1.f - fy) * a;
            cw[pt][1] = fx * (1.f - fy) * a;
            cw[pt][2] = (1.f - fx) * fy * a;
            cw[pt][3] = fx * fy * a;
        }

        const int xmin = min(min(x0[0], x0[1]), min(x0[2], x0[3]));
        const int ymin = min(min(y0[0], y0[1]), min(y0[2], y0[3]));
        const int xmax = max(max(x0[0], x0[1]), max(x0[2], x0[3]));
        const int ymax = max(max(y0[0], y0[1]), max(y0[2], y0[3]));

        if (xmax - xmin <= 2 && ymax - ymin <= 2) {
            // Fast path: all 16 corners live in a 4x4 window. Lane i holds the
            // accumulated weight of cell i (cell = dy*4 + dx).
            float myw = 0.f;
#pragma unroll
            for (int pt = 0; pt < NP; pt++) {
                const int b = (y0[pt] - ymin) * 4 + (x0[pt] - xmin);
                myw += (lane == b)     ? cw[pt][0] : 0.f;
                myw += (lane == b + 1) ? cw[pt][1] : 0.f;
                myw += (lane == b + 4) ? cw[pt][2] : 0.f;
                myw += (lane == b + 5) ? cw[pt][3] : 0.f;
            }
            unsigned nz = __ballot_sync(0xffffffffu, (lane < 16) && (myw != 0.f));
            while (nz) {
                const int cell = __ffs(nz) - 1;
                nz &= nz - 1;
                const float w = __shfl_sync(0xffffffffu, myw, cell);
                const int xx = xmin + (cell & 3);
                const int yy = ymin + (cell >> 2);
                if ((unsigned)xx < (unsigned)Ws && (unsigned)yy < (unsigned)Hs)
                    GATHER(xx, yy, w);
            }
        } else {
            // Rare fallback: per-point corner loads.
#pragma unroll
            for (int pt = 0; pt < NP; pt++) {
                const int xs[2] = {x0[pt], x0[pt] + 1};
                const int ys[2] = {y0[pt], y0[pt] + 1};
#pragma unroll
                for (int cy = 0; cy < 2; cy++) {
#pragma unroll
                    for (int cx = 0; cx < 2; cx++) {
                        const int xx = xs[cx];
                        const int yy = ys[cy];
                        const float w = cw[pt][cy * 2 + cx];
                        if ((unsigned)xx < (unsigned)Ws && (unsigned)yy < (unsigned)Hs)
                            GATHER(xx, yy, w);
                    }
                }
            }
        }
        loff += (size_t)Hs * (size_t)Ws * CCH;
    }
#undef GATHER

    float4* op = (float4*)(out + (size_t)q * CCH);
    op[lane * 2 + 0] = acc0;
    op[lane * 2 + 1] = acc1;
}

extern "C" void kernel_launch(void* const* d_in, const int* in_sizes, int n_in,
                              void* d_out, int out_size)
{
    const float* query   = (const float*)d_in[0];
    // d_in[1] = key (unused)
    const float* value   = (const float*)d_in[2];
    const float* refpts  = (const float*)d_in[3];
    const int*   shapes  = (const int*)d_in[4];
    const float* W_off   = (const float*)d_in[5];
    const float* b_off   = (const float*)d_in[6];
    const float* W_attn  = (const float*)d_in[7];
    const float* b_attn  = (const float*)d_in[8];
    float*       out     = (float*)d_out;

    const int Q = in_sizes[0] / CCH;

    proj_kernel<<<(Q + K1_BLOCK - 1) / K1_BLOCK, K1_BLOCK>>>(
        query, W_off, b_off, W_attn, b_attn, Q);
    sample_kernel<<<(Q + WPB - 1) / WPB, WPB * 32>>>(
        value, refpts, shapes, out, Q);
}